// round 1
// baseline (speedup 1.0000x reference)
#include <cuda_runtime.h>
#include <cstdint>

#define NMAX 100000
#define EMAX 1600000
#define DIN 128

// ---------------- device scratch (static: no allocations allowed) ----------------
__device__ int   g_deg[NMAX];
__device__ int   g_rowptr[NMAX + 1];
__device__ int   g_cursor[NMAX];
__device__ int   g_adj[EMAX];
__device__ float g_deginv[NMAX];
__device__ int   g_part[128];
__device__ float g_h0[(size_t)NMAX * DIN];
__device__ float g_h1[(size_t)NMAX * DIN];
__device__ float g_agg[(size_t)NMAX * DIN];

// ---------------- CSR build ----------------
__global__ void k_zero_deg(int n) {
    int i = blockIdx.x * blockDim.x + threadIdx.x;
    if (i < n) g_deg[i] = 0;
}

__global__ void k_count(const int* __restrict__ dst, int e) {
    int i = blockIdx.x * blockDim.x + threadIdx.x;
    if (i < e) atomicAdd(&g_deg[dst[i]], 1);
}

// per-block exclusive scan of degrees (1024 elems/block), block sums -> g_part
__global__ void k_scan_block(int n) {
    __shared__ int s[1024];
    int tid = threadIdx.x;
    int i = blockIdx.x * 1024 + tid;
    int v = (i < n) ? g_deg[i] : 0;
    s[tid] = v;
    __syncthreads();
    for (int off = 1; off < 1024; off <<= 1) {
        int t = (tid >= off) ? s[tid - off] : 0;
        __syncthreads();
        s[tid] += t;
        __syncthreads();
    }
    if (i < n) g_rowptr[i] = s[tid] - v;   // exclusive within block
    if (tid == 1023) g_part[blockIdx.x] = s[1023];
}

// scan the (<=128) block partials in-place (exclusive)
__global__ void k_scan_part(int nb) {
    __shared__ int s[128];
    int t = threadIdx.x;
    s[t] = (t < nb) ? g_part[t] : 0;
    __syncthreads();
    if (t == 0) {
        int run = 0;
        for (int i = 0; i < nb; ++i) { int v = s[i]; s[i] = run; run += v; }
    }
    __syncthreads();
    if (t < nb) g_part[t] = s[t];
}

__global__ void k_apply(int n, int e) {
    int i = blockIdx.x * blockDim.x + threadIdx.x;
    if (i < n) {
        int v = g_rowptr[i] + g_part[i >> 10];
        g_rowptr[i] = v;
        g_cursor[i] = v;
    }
    if (i == 0) g_rowptr[n] = e;
}

__global__ void k_fill(const int* __restrict__ src, const int* __restrict__ dst, int e) {
    int i = blockIdx.x * blockDim.x + threadIdx.x;
    if (i < e) {
        int d = dst[i];
        int p = atomicAdd(&g_cursor[d], 1);
        g_adj[p] = src[i];
    }
}

__global__ void k_deginv(int n) {
    int i = blockIdx.x * blockDim.x + threadIdx.x;
    if (i < n) g_deginv[i] = 1.0f / fmaxf((float)g_deg[i], 1.0f);
}

// ---------------- aggregation: one warp per node, float4 lanes ----------------
__global__ void k_agg(const float* __restrict__ hin, float* __restrict__ agg, int n) {
    int nid = blockIdx.x * 8 + (threadIdx.x >> 5);
    if (nid >= n) return;
    int lane = threadIdx.x & 31;
    int s = g_rowptr[nid];
    int e = g_rowptr[nid + 1];
    const float4* h4 = (const float4*)hin;
    float4 a0 = {0.f, 0.f, 0.f, 0.f};
    float4 a1 = {0.f, 0.f, 0.f, 0.f};
    int j = s;
    for (; j + 1 < e; j += 2) {
        int v0 = g_adj[j];
        int v1 = g_adj[j + 1];
        float4 t0 = h4[(size_t)v0 * 32 + lane];
        float4 t1 = h4[(size_t)v1 * 32 + lane];
        a0.x += t0.x; a0.y += t0.y; a0.z += t0.z; a0.w += t0.w;
        a1.x += t1.x; a1.y += t1.y; a1.z += t1.z; a1.w += t1.w;
    }
    if (j < e) {
        int v = g_adj[j];
        float4 t = h4[(size_t)v * 32 + lane];
        a0.x += t.x; a0.y += t.y; a0.z += t.z; a0.w += t.w;
    }
    float di = g_deginv[nid];
    float4 o;
    o.x = (a0.x + a1.x) * di;
    o.y = (a0.y + a1.y) * di;
    o.z = (a0.z + a1.z) * di;
    o.w = (a0.w + a1.w) * di;
    ((float4*)agg)[(size_t)nid * 32 + lane] = o;
}

// ---------------- fused GEMM: out = act( hin@W0 + agg@W1 + b ) ----------------
// Block = 256 threads covers 64 rows x DOUT cols; full 256xDOUT weight in smem.
// Thread tile: 4 rows x TN cols, cols interleaved (tx + 16*i) for conflict-free LDS.
template <int DOUT, bool RELU>
__global__ __launch_bounds__(256, 1)
void k_gemm(const float* __restrict__ A0, const float* __restrict__ A1,
            const float* __restrict__ W0, const float* __restrict__ W1,
            const float* __restrict__ bias, float* __restrict__ out, int n) {
    constexpr int TN = DOUT / 16;
    constexpr int AS = 260;               // padded A row stride (floats)
    extern __shared__ float sm[];
    float* Wsm = sm;                      // [256][DOUT]
    float* Asm = sm + 256 * DOUT;         // [64][AS]
    int tid = threadIdx.x;

    // load weights (k 0..127 = W0, 128..255 = W1)
    constexpr int WQ = 128 * DOUT / 4;
    const float4* W04 = (const float4*)W0;
    const float4* W14 = (const float4*)W1;
    float4* Wsm4 = (float4*)Wsm;
    for (int idx = tid; idx < WQ; idx += 256) {
        Wsm4[idx]      = W04[idx];
        Wsm4[WQ + idx] = W14[idx];
    }

    // load A tile: 64 rows x 256 (hin | agg)
    int row0 = blockIdx.x * 64;
    for (int f = tid; f < 64 * 32; f += 256) {
        int r  = f >> 5;
        int c4 = f & 31;
        int row = row0 + r;
        float4 a = {0.f, 0.f, 0.f, 0.f};
        float4 b = {0.f, 0.f, 0.f, 0.f};
        if (row < n) {
            a = ((const float4*)(A0 + (size_t)row * 128))[c4];
            b = ((const float4*)(A1 + (size_t)row * 128))[c4];
        }
        *(float4*)&Asm[r * AS + c4 * 4]       = a;
        *(float4*)&Asm[r * AS + 128 + c4 * 4] = b;
    }
    __syncthreads();

    int tx = tid & 15;   // column group: cols tx + 16*i
    int ty = tid >> 4;   // row group: rows ty*4 .. ty*4+3

    float acc[4][TN];
#pragma unroll
    for (int r = 0; r < 4; ++r)
#pragma unroll
        for (int i = 0; i < TN; ++i) acc[r][i] = 0.f;

    for (int k = 0; k < 256; k += 4) {
        float4 a4[4];
#pragma unroll
        for (int r = 0; r < 4; ++r)
            a4[r] = *(const float4*)&Asm[(ty * 4 + r) * AS + k];
#pragma unroll
        for (int kk = 0; kk < 4; ++kk) {
            float w[TN];
#pragma unroll
            for (int i = 0; i < TN; ++i) w[i] = Wsm[(k + kk) * DOUT + tx + 16 * i];
#pragma unroll
            for (int r = 0; r < 4; ++r) {
                float av = ((const float*)&a4[r])[kk];
#pragma unroll
                for (int i = 0; i < TN; ++i) acc[r][i] = fmaf(av, w[i], acc[r][i]);
            }
        }
    }

#pragma unroll
    for (int r = 0; r < 4; ++r) {
        int row = row0 + ty * 4 + r;
        if (row < n) {
#pragma unroll
            for (int i = 0; i < TN; ++i) {
                float v = acc[r][i] + bias[tx + 16 * i];
                if (RELU) v = fmaxf(v, 0.f);
                out[(size_t)row * DOUT + tx + 16 * i] = v;
            }
        }
    }
}

// ---------------- launch ----------------
extern "C" void kernel_launch(void* const* d_in, const int* in_sizes, int n_in,
                              void* d_out, int out_size) {
    const float* x   = (const float*)d_in[0];
    const int*   src = (const int*)d_in[1];
    const int*   dst = (const int*)d_in[2];
    const float* Ws0 = (const float*)d_in[3];
    const float* Wn0 = (const float*)d_in[4];
    const float* b0  = (const float*)d_in[5];
    const float* Ws1 = (const float*)d_in[6];
    const float* Wn1 = (const float*)d_in[7];
    const float* b1  = (const float*)d_in[8];
    const float* Ws2 = (const float*)d_in[9];
    const float* Wn2 = (const float*)d_in[10];
    const float* b2  = (const float*)d_in[11];
    float* out = (float*)d_out;

    int n = in_sizes[0] / 128;
    int e = in_sizes[1];

    float *h0, *h1, *agg;
    cudaGetSymbolAddress((void**)&h0,  g_h0);
    cudaGetSymbolAddress((void**)&h1,  g_h1);
    cudaGetSymbolAddress((void**)&agg, g_agg);

    const int SMEM128 = (256 * 128 + 64 * 260) * 4;   // 197632
    const int SMEM64  = (256 * 64  + 64 * 260) * 4;   // 132096
    cudaFuncSetAttribute(k_gemm<128, true>,
                         cudaFuncAttributeMaxDynamicSharedMemorySize, SMEM128);
    cudaFuncSetAttribute(k_gemm<64, false>,
                         cudaFuncAttributeMaxDynamicSharedMemorySize, SMEM64);

    int nb = (n + 1023) / 1024;

    // CSR build (reused by all 3 layers)
    k_zero_deg<<<(n + 255) / 256, 256>>>(n);
    k_count<<<(e + 255) / 256, 256>>>(dst, e);
    k_scan_block<<<nb, 1024>>>(n);
    k_scan_part<<<1, 128>>>(nb);
    k_apply<<<(n + 255) / 256, 256>>>(n, e);
    k_fill<<<(e + 255) / 256, 256>>>(src, dst, e);
    k_deginv<<<(n + 255) / 256, 256>>>(n);

    int ga = (n + 7) / 8;        // agg: 8 nodes (warps) per block
    int gb = (n + 63) / 64;      // gemm: 64 rows per block

    // layer 0
    k_agg<<<ga, 256>>>(x, agg, n);
    k_gemm<128, true><<<gb, 256, SMEM128>>>(x, agg, Ws0, Wn0, b0, h0, n);
    // layer 1
    k_agg<<<ga, 256>>>(h0, agg, n);
    k_gemm<128, true><<<gb, 256, SMEM128>>>(h0, agg, Ws1, Wn1, b1, h1, n);
    // layer 2
    k_agg<<<ga, 256>>>(h1, agg, n);
    k_gemm<64, false><<<gb, 256, SMEM64>>>(h1, agg, Ws2, Wn2, b2, out, n);
}

// round 3
// speedup vs baseline: 1.8628x; 1.8628x over previous
#include <cuda_runtime.h>
#include <cstdint>

#define NMAX 100000
#define EMAX 1600000
#define DIN 128

// ---------------- device scratch ----------------
__device__ int   g_deg[NMAX];
__device__ int   g_rowptr[NMAX + 1];
__device__ int   g_cursor[NMAX];
__device__ int   g_adj[EMAX];
__device__ float g_deginv[NMAX];
__device__ int   g_part[128];
__device__ float g_h0[(size_t)NMAX * DIN];
__device__ float g_h1[(size_t)NMAX * DIN];
__device__ float g_agg[(size_t)NMAX * DIN];
// weight images in mma-fragment order, tf32-rounded: [Wself|Wneigh] (K=256 x DOUT)
__device__ float g_wt0[256 * 128];
__device__ float g_wt1[256 * 128];
__device__ float g_wt2[256 * 64];

__device__ __forceinline__ uint32_t f2tf32(float v) {
    uint32_t r;
    asm("cvt.rna.tf32.f32 %0, %1;" : "=r"(r) : "f"(v));
    return r;
}

__device__ __forceinline__ void mma8(float* c, const uint32_t* a, const uint32_t* b) {
    asm volatile(
        "mma.sync.aligned.m16n8k8.row.col.f32.tf32.tf32.f32 "
        "{%0,%1,%2,%3}, {%4,%5,%6,%7}, {%8,%9}, {%0,%1,%2,%3};"
        : "+f"(c[0]), "+f"(c[1]), "+f"(c[2]), "+f"(c[3])
        : "r"(a[0]), "r"(a[1]), "r"(a[2]), "r"(a[3]), "r"(b[0]), "r"(b[1]));
}

// ---------------- CSR build ----------------
__global__ void k_zero_deg(int n) {
    int i = blockIdx.x * blockDim.x + threadIdx.x;
    if (i < n) g_deg[i] = 0;
}
__global__ void k_count(const int* __restrict__ dst, int e) {
    int i = blockIdx.x * blockDim.x + threadIdx.x;
    if (i < e) atomicAdd(&g_deg[dst[i]], 1);
}
__global__ void k_scan_block(int n) {
    __shared__ int s[1024];
    int tid = threadIdx.x;
    int i = blockIdx.x * 1024 + tid;
    int v = (i < n) ? g_deg[i] : 0;
    s[tid] = v;
    __syncthreads();
    for (int off = 1; off < 1024; off <<= 1) {
        int t = (tid >= off) ? s[tid - off] : 0;
        __syncthreads();
        s[tid] += t;
        __syncthreads();
    }
    if (i < n) g_rowptr[i] = s[tid] - v;
    if (tid == 1023) g_part[blockIdx.x] = s[1023];
}
__global__ void k_scan_part(int nb) {
    __shared__ int s[128];
    int t = threadIdx.x;
    int v = (t < nb) ? g_part[t] : 0;
    s[t] = v;
    __syncthreads();
    for (int off = 1; off < 128; off <<= 1) {
        int u = (t >= off) ? s[t - off] : 0;
        __syncthreads();
        s[t] += u;
        __syncthreads();
    }
    if (t < nb) g_part[t] = s[t] - v;   // exclusive
}
__global__ void k_apply(int n, int e) {
    int i = blockIdx.x * blockDim.x + threadIdx.x;
    if (i < n) {
        int v = g_rowptr[i] + g_part[i >> 10];
        g_rowptr[i] = v;
        g_cursor[i] = v;
    }
    if (i == 0) g_rowptr[n] = e;
}
__global__ void k_fill(const int* __restrict__ src, const int* __restrict__ dst, int e) {
    int i = blockIdx.x * blockDim.x + threadIdx.x;
    if (i < e) {
        int p = atomicAdd(&g_cursor[dst[i]], 1);
        g_adj[p] = src[i];
    }
}
__global__ void k_deginv(int n) {
    int i = blockIdx.x * blockDim.x + threadIdx.x;
    if (i < n) g_deginv[i] = 1.0f / fmaxf((float)g_deg[i], 1.0f);
}

// ---------------- aggregation: warp per node ----------------
__global__ void k_agg(const float* __restrict__ hin, float* __restrict__ agg, int n) {
    int nid = blockIdx.x * 8 + (threadIdx.x >> 5);
    if (nid >= n) return;
    int lane = threadIdx.x & 31;
    int s = g_rowptr[nid];
    int e = g_rowptr[nid + 1];
    const float4* h4 = (const float4*)hin;
    float4 a0 = {0.f, 0.f, 0.f, 0.f};
    float4 a1 = {0.f, 0.f, 0.f, 0.f};
    int j = s;
    for (; j + 1 < e; j += 2) {
        int v0 = g_adj[j];
        int v1 = g_adj[j + 1];
        float4 t0 = h4[(size_t)v0 * 32 + lane];
        float4 t1 = h4[(size_t)v1 * 32 + lane];
        a0.x += t0.x; a0.y += t0.y; a0.z += t0.z; a0.w += t0.w;
        a1.x += t1.x; a1.y += t1.y; a1.z += t1.z; a1.w += t1.w;
    }
    if (j < e) {
        int v = g_adj[j];
        float4 t = h4[(size_t)v * 32 + lane];
        a0.x += t.x; a0.y += t.y; a0.z += t.z; a0.w += t.w;
    }
    float di = g_deginv[nid];
    float4 o;
    o.x = (a0.x + a1.x) * di;
    o.y = (a0.y + a1.y) * di;
    o.z = (a0.z + a1.z) * di;
    o.w = (a0.w + a1.w) * di;
    ((float4*)agg)[(size_t)nid * 32 + lane] = o;
}

// ---------------- W preprocessing: fragment-order, tf32-rounded B image ----------------
// B fragment (m16n8k8.row.col): lane=((n&7)<<2)|(k&3), reg=k>>2 (within 8x8 tile)
// image index: ((ksg*(DOUT/8) + nt)*32 + lane)*2 + reg
__global__ void k_prepw(const float* __restrict__ Wa, const float* __restrict__ Wb,
                        float* __restrict__ o, int dout) {
    int i = blockIdx.x * blockDim.x + threadIdx.x;
    if (i >= 256 * dout) return;
    int k = i / dout, nn = i % dout;
    float v = (k < 128) ? Wa[k * dout + nn] : Wb[(k - 128) * dout + nn];
    int ksg = k >> 3, nt = nn >> 3;
    int lane = ((nn & 7) << 2) | (k & 3);
    int reg = (k >> 2) & 1;
    o[((ksg * (dout >> 3) + nt) * 32 + lane) * 2 + reg] = __uint_as_float(f2tf32(v));
}

// ---------------- tf32 mma.sync GEMM ----------------
// C[128 x DOUT] = [h|agg][128 x 256] @ W[256 x DOUT] + b (relu optional)
// 8 warps: wm=wid>>1 (32 rows), wn=wid&1 (DOUT/2 cols). NT n-tiles of 8 per warp.
template <int DOUT, bool RELU>
__global__ __launch_bounds__(256)
void k_mma(const float* __restrict__ A0, const float* __restrict__ A1,
           const float* __restrict__ Wt, const float* __restrict__ bias,
           float* __restrict__ out, int n) {
    constexpr int NT = DOUT / 16;            // n-tiles per warp
    constexpr int WFLOATS = 256 * DOUT;
    constexpr int STG_FLOATS = 8192;         // one A stage: 128 rows x 64 k
    extern __shared__ float sm[];
    float* Wsm = sm;
    float* Asm = sm + WFLOATS;
    int tid = threadIdx.x, wid = tid >> 5, lane = tid & 31;
    int row0 = blockIdx.x * 128;

    // W image copy (already fragment-ordered + tf32)
    {
        const float4* g = (const float4*)Wt;
        float4* s = (float4*)Wsm;
        for (int i = tid; i < WFLOATS / 4; i += 256) s[i] = g[i];
    }

    // --- chunk LDG: 128 rows x 64 cols (quarter q of [A0|A1]) into regs ---
    auto ldg_chunk = [&](int q, float4* v) {
        const float* src = (q < 2) ? A0 : A1;
        int cb4 = (q & 1) * 16;
#pragma unroll
        for (int u = 0; u < 8; ++u) {
            int i = tid + u * 256;
            int r = i >> 4, c4 = i & 15;
            int grow = row0 + r;
            float4 t = {0.f, 0.f, 0.f, 0.f};
            if (grow < n) t = ((const float4*)src)[(size_t)grow * 32 + cb4 + c4];
            v[u] = t;
        }
    };
    // --- STS in A-fragment order: lane=((r&7)<<2)|(col&3), reg=((r>>3)&1)|((col>=4)<<1)
    auto sts_chunk = [&](float* stage, const float4* v) {
#pragma unroll
        for (int u = 0; u < 8; ++u) {
            int i = tid + u * 256;
            int r = i >> 4, c4 = i & 15;
            int ks = c4 >> 1, mt = r >> 4;
            int lanebase = (r & 7) << 2;
            int reg = ((r >> 3) & 1) | ((c4 & 1) << 1);
            float* base = stage + ((ks * 8 + mt) * 32 + lanebase) * 4 + reg;
            base[0]  = __uint_as_float(f2tf32(v[u].x));
            base[4]  = __uint_as_float(f2tf32(v[u].y));
            base[8]  = __uint_as_float(f2tf32(v[u].z));
            base[12] = __uint_as_float(f2tf32(v[u].w));
        }
    };

    float acc[2][NT][4];
#pragma unroll
    for (int i = 0; i < 2; ++i)
#pragma unroll
        for (int j = 0; j < NT; ++j)
#pragma unroll
            for (int t = 0; t < 4; ++t) acc[i][j][t] = 0.f;

    int wm = wid >> 1, wn = wid & 1;

    float4 v[8];
    ldg_chunk(0, v);
    sts_chunk(Asm, v);
    __syncthreads();

#pragma unroll
    for (int q = 0; q < 4; ++q) {
        float4 nv[8];
        if (q < 3) ldg_chunk(q + 1, nv);

        const float* stage = Asm + (q & 1) * STG_FLOATS;
#pragma unroll
        for (int ks = 0; ks < 8; ++ks) {
            int ksg = q * 8 + ks;
            uint32_t afr[2][4];
#pragma unroll
            for (int i = 0; i < 2; ++i) {
                int mt = wm * 2 + i;
                float4 t = *(const float4*)(stage + ((ks * 8 + mt) * 32 + lane) * 4);
                afr[i][0] = __float_as_uint(t.x);
                afr[i][1] = __float_as_uint(t.y);
                afr[i][2] = __float_as_uint(t.z);
                afr[i][3] = __float_as_uint(t.w);
            }
#pragma unroll
            for (int j = 0; j < NT; ++j) {
                int ntg = wn * NT + j;
                float2 t = *(const float2*)(Wsm + ((ksg * (DOUT / 8) + ntg) * 32 + lane) * 2);
                uint32_t bfr[2] = {__float_as_uint(t.x), __float_as_uint(t.y)};
                mma8(acc[0][j], afr[0], bfr);
                mma8(acc[1][j], afr[1], bfr);
            }
        }

        if (q < 3) {
            __syncthreads();
            sts_chunk(Asm + ((q + 1) & 1) * STG_FLOATS, nv);
            __syncthreads();
        }
    }

    // epilogue
#pragma unroll
    for (int i = 0; i < 2; ++i) {
        int r0g = row0 + wm * 32 + i * 16 + (lane >> 2);
#pragma unroll
        for (int j = 0; j < NT; ++j) {
            int cb = wn * (NT * 8) + j * 8 + (lane & 3) * 2;
            float b0 = bias[cb], b1 = bias[cb + 1];
            float2 o0, o1;
            o0.x = acc[i][j][0] + b0; o0.y = acc[i][j][1] + b1;
            o1.x = acc[i][j][2] + b0; o1.y = acc[i][j][3] + b1;
            if (RELU) {
                o0.x = fmaxf(o0.x, 0.f); o0.y = fmaxf(o0.y, 0.f);
                o1.x = fmaxf(o1.x, 0.f); o1.y = fmaxf(o1.y, 0.f);
            }
            if (r0g < n)     *(float2*)(out + (size_t)r0g * DOUT + cb) = o0;
            if (r0g + 8 < n) *(float2*)(out + (size_t)(r0g + 8) * DOUT + cb) = o1;
        }
    }
}

// ---------------- launch ----------------
extern "C" void kernel_launch(void* const* d_in, const int* in_sizes, int n_in,
                              void* d_out, int out_size) {
    const float* x   = (const float*)d_in[0];
    const int*   src = (const int*)d_in[1];
    const int*   dst = (const int*)d_in[2];
    const float* Ws0 = (const float*)d_in[3];
    const float* Wn0 = (const float*)d_in[4];
    const float* b0  = (const float*)d_in[5];
    const float* Ws1 = (const float*)d_in[6];
    const float* Wn1 = (const float*)d_in[7];
    const float* b1  = (const float*)d_in[8];
    const float* Ws2 = (const float*)d_in[9];
    const float* Wn2 = (const float*)d_in[10];
    const float* b2  = (const float*)d_in[11];
    float* out = (float*)d_out;

    int n = in_sizes[0] / 128;
    int e = in_sizes[1];

    float *h0, *h1, *agg, *wt0, *wt1, *wt2;
    cudaGetSymbolAddress((void**)&h0,  g_h0);
    cudaGetSymbolAddress((void**)&h1,  g_h1);
    cudaGetSymbolAddress((void**)&agg, g_agg);
    cudaGetSymbolAddress((void**)&wt0, g_wt0);
    cudaGetSymbolAddress((void**)&wt1, g_wt1);
    cudaGetSymbolAddress((void**)&wt2, g_wt2);

    const int SM128 = (256 * 128 + 2 * 8192) * 4;   // 196608
    const int SM64  = (256 * 64  + 2 * 8192) * 4;   // 131072
    cudaFuncSetAttribute(k_mma<128, true>,
                         cudaFuncAttributeMaxDynamicSharedMemorySize, SM128);
    cudaFuncSetAttribute(k_mma<64, false>,
                         cudaFuncAttributeMaxDynamicSharedMemorySize, SM64);

    // W preprocessing (fragment order + tf32 round)
    k_prepw<<<(256 * 128 + 255) / 256, 256>>>(Ws0, Wn0, wt0, 128);
    k_prepw<<<(256 * 128 + 255) / 256, 256>>>(Ws1, Wn1, wt1, 128);
    k_prepw<<<(256 * 64 + 255) / 256, 256>>>(Ws2, Wn2, wt2, 64);

    // CSR build
    int nb = (n + 1023) / 1024;
    k_zero_deg<<<(n + 255) / 256, 256>>>(n);
    k_count<<<(e + 255) / 256, 256>>>(dst, e);
    k_scan_block<<<nb, 1024>>>(n);
    k_scan_part<<<1, 128>>>(nb);
    k_apply<<<(n + 255) / 256, 256>>>(n, e);
    k_fill<<<(e + 255) / 256, 256>>>(src, dst, e);
    k_deginv<<<(n + 255) / 256, 256>>>(n);

    int ga = (n + 7) / 8;
    int gm = (n + 127) / 128;

    k_agg<<<ga, 256>>>(x, agg, n);
    k_mma<128, true><<<gm, 256, SM128>>>(x, agg, wt0, b0, h0, n);
    k_agg<<<ga, 256>>>(h0, agg, n);
    k_mma<128, true><<<gm, 256, SM128>>>(h0, agg, wt1, b1, h1, n);
    k_agg<<<ga, 256>>>(h1, agg, n);
    k_mma<64, false><<<gm, 256, SM64>>>(h1, agg, wt2, b2, out, n);
}